// round 2
// baseline (speedup 1.0000x reference)
#include <cuda_runtime.h>
#include <cuda_bf16.h>
#include <math.h>

// ---------------- problem constants ----------------
#define NN 512        // sequence length
#define CS 384        // s channels
#define CZ 128        // z channels
#define NH 8          // heads
#define CH 256        // per-head channels
#define PQ_ 8
#define PV_ 12
#define FEAT 2688     // H*(C + 4*PV + CZ/4) = 8*336

// ---------------- scratch (device globals; no allocation allowed) ----------------
__device__ float g_qbuf [NN * NH * CH];          // 512 x 2048
__device__ float g_kvbuf[NN * NH * 2 * CH];      // 512 x 4096
__device__ float g_qpraw[NN * NH * PQ_ * 3];     // 512 x 192
__device__ float g_kvpraw[NN * NH * (PQ_+PV_) * 3]; // 512 x 480
__device__ float g_qpts [NN * NH * PQ_ * 3];     // [n][h][p][d]
__device__ float g_kpts [NN * NH * PQ_ * 3];
__device__ float g_vpts [NN * NH * PV_ * 3];     // [n][h][p][d] (36 per head)
__device__ float g_biasz[NN * NN * NH];          // [i][j][h]
__device__ float g_pairz[(long)NN * NN * 32];    // [i][j][32]
__device__ float g_logits[(long)NH * NN * NN];   // [h][i][j] -> becomes attn after softmax
__device__ float g_optbuf[NH * NN * 36];         // [h][i][p*3+d]
__device__ float g_feats [NN * FEAT];            // concat features

// ---------------- generic batched tiled SGEMM: C = A@B (+bias) ----------------
// A: M x K row-major (lda), B: K x N row-major (ldb), C: M x N (ldc)
// batch over blockIdx.z with element strides sAz, sBz, sCz.
__global__ void sgemm_nn(const float* __restrict__ A, int lda, long sAz,
                         const float* __restrict__ B, int ldb, long sBz,
                         float* __restrict__ C, int ldc, long sCz,
                         int M, int N, int K,
                         const float* __restrict__ bias)
{
    __shared__ float As[16][65];
    __shared__ float Bs[16][64];
    const int tid = threadIdx.x;
    const int tx = tid & 15, ty = tid >> 4;
    const int row0 = blockIdx.y * 64;
    const int col0 = blockIdx.x * 64;
    const float* Ab = A + (long)blockIdx.z * sAz;
    const float* Bb = B + (long)blockIdx.z * sBz;
    float* Cb = C + (long)blockIdx.z * sCz;

    float acc[4][4];
#pragma unroll
    for (int m = 0; m < 4; m++)
#pragma unroll
        for (int n = 0; n < 4; n++) acc[m][n] = 0.f;

    for (int k0 = 0; k0 < K; k0 += 16) {
#pragma unroll
        for (int i = 0; i < 4; i++) {
            int idx = tid + i * 256;
            int r = idx >> 4, kk = idx & 15;
            int gr = row0 + r, gk = k0 + kk;
            As[kk][r] = (gr < M && gk < K) ? Ab[(long)gr * lda + gk] : 0.f;
        }
#pragma unroll
        for (int i = 0; i < 4; i++) {
            int idx = tid + i * 256;
            int kk = idx >> 6, c = idx & 63;
            int gk = k0 + kk, gc = col0 + c;
            Bs[kk][c] = (gk < K && gc < N) ? Bb[(long)gk * ldb + gc] : 0.f;
        }
        __syncthreads();
#pragma unroll
        for (int kk = 0; kk < 16; kk++) {
            float a[4];
#pragma unroll
            for (int m = 0; m < 4; m++) a[m] = As[kk][ty * 4 + m];
            float4 b4 = *(const float4*)&Bs[kk][tx * 4];
            float b[4] = {b4.x, b4.y, b4.z, b4.w};
#pragma unroll
            for (int m = 0; m < 4; m++)
#pragma unroll
                for (int n = 0; n < 4; n++) acc[m][n] += a[m] * b[n];
        }
        __syncthreads();
    }
#pragma unroll
    for (int m = 0; m < 4; m++) {
        int gr = row0 + ty * 4 + m;
        if (gr >= M) continue;
#pragma unroll
        for (int n = 0; n < 4; n++) {
            int gc = col0 + tx * 4 + n;
            if (gc >= N) continue;
            float v = acc[m][n];
            if (bias) v += bias[gc];
            Cb[(long)gr * ldc + gc] = v;
        }
    }
}

// ---------------- rigid transform of point projections ----------------
// qpraw: [n][d*64 + p] (p = h*8+pq), kvpraw: [n][d*160 + p] (p = h*20+pp)
__global__ void rigid_kernel(const float* __restrict__ qpraw,
                             const float* __restrict__ kvpraw,
                             const float* __restrict__ rot,
                             const float* __restrict__ trans)
{
    int idx = blockIdx.x * 256 + threadIdx.x;
    if (idx >= NN * 224) return;
    int n = idx / 224, p = idx % 224;
    const float* R = rot + n * 9;
    const float* T = trans + n * 3;
    float lx, ly, lz;
    if (p < 64) {
        lx = qpraw[n * 192 + p];
        ly = qpraw[n * 192 + 64 + p];
        lz = qpraw[n * 192 + 128 + p];
    } else {
        int pp = p - 64;
        lx = kvpraw[n * 480 + pp];
        ly = kvpraw[n * 480 + 160 + pp];
        lz = kvpraw[n * 480 + 320 + pp];
    }
    float gx = R[0]*lx + R[1]*ly + R[2]*lz + T[0];
    float gy = R[3]*lx + R[4]*ly + R[5]*lz + T[1];
    float gz = R[6]*lx + R[7]*ly + R[8]*lz + T[2];
    if (p < 64) {
        int h = p >> 3, pq = p & 7;
        float* d = g_qpts + n * 192 + h * 24 + pq * 3;
        d[0] = gx; d[1] = gy; d[2] = gz;
    } else {
        int pp = p - 64;
        int h = pp / 20, q = pp % 20;
        if (q < 8) {
            float* d = g_kpts + n * 192 + h * 24 + q * 3;
            d[0] = gx; d[1] = gy; d[2] = gz;
        } else {
            float* d = g_vpts + n * 288 + h * 36 + (q - 8) * 3;
            d[0] = gx; d[1] = gy; d[2] = gz;
        }
    }
}

// ---------------- fused z projections (read z once) ----------------
// per (i,j): bias[8] = z.wb + bb ; pairz[32] = z.wz + bz
__global__ void zproj_kernel(const float* __restrict__ z,
                             const float* __restrict__ wb, const float* __restrict__ bb,
                             const float* __restrict__ wz, const float* __restrict__ bz)
{
    __shared__ float ws[128][40];
    int tid = threadIdx.x;
    for (int i = tid; i < 128 * 40; i += 256) {
        int c = i / 40, d = i % 40;
        ws[c][d] = (d < 8) ? wb[c * 8 + d] : wz[c * 32 + (d - 8)];
    }
    __syncthreads();
    long pair = (long)blockIdx.x * 256 + tid;   // 262144 pairs
    const float4* zr = (const float4*)(z + pair * 128);
    float acc[40];
#pragma unroll
    for (int d = 0; d < 40; d++) acc[d] = 0.f;
#pragma unroll 2
    for (int c4 = 0; c4 < 32; c4++) {
        float4 zv = zr[c4];
        int c = c4 * 4;
#pragma unroll
        for (int d = 0; d < 40; d++) acc[d] += zv.x * ws[c][d];
#pragma unroll
        for (int d = 0; d < 40; d++) acc[d] += zv.y * ws[c + 1][d];
#pragma unroll
        for (int d = 0; d < 40; d++) acc[d] += zv.z * ws[c + 2][d];
#pragma unroll
        for (int d = 0; d < 40; d++) acc[d] += zv.w * ws[c + 3][d];
    }
#pragma unroll
    for (int d = 0; d < 8; d++)  g_biasz[pair * 8 + d]  = acc[d] + bb[d];
#pragma unroll
    for (int d = 0; d < 32; d++) g_pairz[pair * 32 + d] = acc[8 + d] + bz[d];
}

// ---------------- attention logits: qk + point term + pair bias + mask ----------------
__global__ void logits_kernel(const float* __restrict__ mask,
                              const float* __restrict__ head_w)
{
    const int h = blockIdx.z;
    __shared__ float As[16][65];
    __shared__ float Bs[16][64];
    __shared__ float qp_s[64][25];
    __shared__ float kp_s[64][25];
    __shared__ float mi_s[64], mj_s[64];
    const int tid = threadIdx.x;
    const int tx = tid & 15, ty = tid >> 4;
    const int row0 = blockIdx.y * 64;
    const int col0 = blockIdx.x * 64;
    const float* A = g_qbuf + h * 256;       // q[i][h][c], lda 2048
    const float* Bk = g_kvbuf + h * 512;     // k[j][h][c], row-stride 4096

    float acc[4][4];
#pragma unroll
    for (int m = 0; m < 4; m++)
#pragma unroll
        for (int n = 0; n < 4; n++) acc[m][n] = 0.f;

    for (int k0 = 0; k0 < 256; k0 += 16) {
#pragma unroll
        for (int i = 0; i < 4; i++) {
            int idx = tid + i * 256;
            int r = idx >> 4, kk = idx & 15;
            As[kk][r] = A[(long)(row0 + r) * 2048 + k0 + kk];
        }
#pragma unroll
        for (int i = 0; i < 4; i++) {
            int idx = tid + i * 256;
            int c = idx >> 4, kk = idx & 15;
            Bs[kk][c] = Bk[(long)(col0 + c) * 4096 + k0 + kk];
        }
        __syncthreads();
#pragma unroll
        for (int kk = 0; kk < 16; kk++) {
            float a[4];
#pragma unroll
            for (int m = 0; m < 4; m++) a[m] = As[kk][ty * 4 + m];
            float4 b4 = *(const float4*)&Bs[kk][tx * 4];
            float b[4] = {b4.x, b4.y, b4.z, b4.w};
#pragma unroll
            for (int m = 0; m < 4; m++)
#pragma unroll
                for (int n = 0; n < 4; n++) acc[m][n] += a[m] * b[n];
        }
        __syncthreads();
    }

    // stage point coords + mask
    for (int idx = tid; idx < 64 * 24; idx += 256) {
        int r = idx / 24, d = idx % 24;
        qp_s[r][d] = g_qpts[(row0 + r) * 192 + h * 24 + d];
        kp_s[r][d] = g_kpts[(col0 + r) * 192 + h * 24 + d];
    }
    if (tid < 64) { mi_s[tid] = mask[row0 + tid]; mj_s[tid] = mask[col0 + tid]; }
    __syncthreads();

    float w = head_w[h];
    float sp = (w > 20.f) ? w : log1pf(expf(w));
    const float hw = sp * 0.09622504486493762f;          // sqrt(1/108)
    const float scale = 0.036084391824351615f;            // sqrt(1/(3*256))
    const float bcoef = 0.5773502691896258f;              // sqrt(1/3)

#pragma unroll
    for (int m = 0; m < 4; m++) {
        int lr = ty * 4 + m;
        int gr = row0 + lr;
#pragma unroll
        for (int n = 0; n < 4; n++) {
            int lc = tx * 4 + n;
            int gc = col0 + lc;
            float pt = 0.f;
#pragma unroll
            for (int p = 0; p < 8; p++) {
                float dx = qp_s[lr][p * 3 + 0] - kp_s[lc][p * 3 + 0];
                float dy = qp_s[lr][p * 3 + 1] - kp_s[lc][p * 3 + 1];
                float dz = qp_s[lr][p * 3 + 2] - kp_s[lc][p * 3 + 2];
                pt += dx * dx + dy * dy + dz * dz;
            }
            float v = acc[m][n] * scale
                    + bcoef * g_biasz[((long)gr * 512 + gc) * 8 + h]
                    - 0.5f * hw * pt
                    + 100000.0f * (mi_s[lr] * mj_s[lc] - 1.0f);
            g_logits[((long)h * 512 + gr) * 512 + gc] = v;
        }
    }
}

// ---------------- row softmax over j (in place) ----------------
__global__ void softmax_kernel()
{
    __shared__ float red[256];
    float* row = g_logits + (long)blockIdx.x * 512;
    int t = threadIdx.x;
    float v1 = row[t], v2 = row[t + 256];
    float m = fmaxf(v1, v2);
    red[t] = m; __syncthreads();
    for (int s = 128; s > 0; s >>= 1) {
        if (t < s) red[t] = fmaxf(red[t], red[t + s]);
        __syncthreads();
    }
    m = red[0]; __syncthreads();
    float e1 = __expf(v1 - m), e2 = __expf(v2 - m);
    red[t] = e1 + e2; __syncthreads();
    for (int s = 128; s > 0; s >>= 1) {
        if (t < s) red[t] += red[t + s];
        __syncthreads();
    }
    float inv = 1.0f / red[0];
    row[t] = e1 * inv; row[t + 256] = e2 * inv;
}

// ---------------- o_pt inverse rigid + norm into feats ----------------
__global__ void optfinal_kernel(const float* __restrict__ rot,
                                const float* __restrict__ trans)
{
    int idx = blockIdx.x * 256 + threadIdx.x;
    if (idx >= NN * 96) return;
    int n = idx / 96, hp = idx % 96;
    int h = hp / 12, p = hp % 12;
    const float* o = g_optbuf + ((long)h * 512 + n) * 36 + p * 3;
    float x = o[0] - trans[n * 3 + 0];
    float y = o[1] - trans[n * 3 + 1];
    float zc = o[2] - trans[n * 3 + 2];
    const float* R = rot + n * 9;
    // out[i] = sum_j R[j][i]*v[j]  (R^T v)
    float ox = R[0] * x + R[3] * y + R[6] * zc;
    float oy = R[1] * x + R[4] * y + R[7] * zc;
    float oz = R[2] * x + R[5] * y + R[8] * zc;
    float* f = g_feats + (long)n * FEAT;
    f[2048 + 0 * 96 + hp] = ox;
    f[2048 + 1 * 96 + hp] = oy;
    f[2048 + 2 * 96 + hp] = oz;
    f[2336 + hp] = sqrtf(ox * ox + oy * oy + oz * oz + 1e-8f);
}

// ---------------- o_pair: per-i batched (8x512)@(512x32) ----------------
__global__ void opair_kernel()
{
    __shared__ float as[8][512];
    int i = blockIdx.x, t = threadIdx.x;
    for (int idx = t; idx < 8 * 512; idx += 256) {
        int h = idx >> 9, j = idx & 511;
        as[h][j] = g_logits[((long)h * 512 + i) * 512 + j];
    }
    __syncthreads();
    int h = t >> 5, d = t & 31;
    const float* pz = g_pairz + (long)i * 512 * 32 + d;
    float acc = 0.f;
#pragma unroll 4
    for (int j = 0; j < 512; j++) acc += as[h][j] * pz[(long)j * 32];
    g_feats[(long)i * FEAT + 2432 + h * 32 + d] = acc;
}

// ---------------- launch ----------------
extern "C" void kernel_launch(void* const* d_in, const int* in_sizes, int n_in,
                              void* d_out, int out_size)
{
    const float* s     = (const float*)d_in[0];
    const float* z     = (const float*)d_in[1];
    const float* rot   = (const float*)d_in[2];
    const float* trans = (const float*)d_in[3];
    const float* mask  = (const float*)d_in[4];
    const float* wq    = (const float*)d_in[5];
    const float* bq    = (const float*)d_in[6];
    const float* wkv   = (const float*)d_in[7];
    const float* bkv   = (const float*)d_in[8];
    const float* wqp   = (const float*)d_in[9];
    const float* bqp   = (const float*)d_in[10];
    const float* wkvp  = (const float*)d_in[11];
    const float* bkvp  = (const float*)d_in[12];
    const float* wb    = (const float*)d_in[13];
    const float* bb    = (const float*)d_in[14];
    const float* wz    = (const float*)d_in[15];
    const float* bz    = (const float*)d_in[16];
    const float* hwt   = (const float*)d_in[17];
    const float* wo    = (const float*)d_in[18];
    const float* bo    = (const float*)d_in[19];
    float* out = (float*)d_out;

    float *qbuf, *kvbuf, *qpraw, *kvpraw, *vpts, *logits, *optbuf, *feats;
    cudaGetSymbolAddress((void**)&qbuf,   g_qbuf);
    cudaGetSymbolAddress((void**)&kvbuf,  g_kvbuf);
    cudaGetSymbolAddress((void**)&qpraw,  g_qpraw);
    cudaGetSymbolAddress((void**)&kvpraw, g_kvpraw);
    cudaGetSymbolAddress((void**)&vpts,   g_vpts);
    cudaGetSymbolAddress((void**)&logits, g_logits);
    cudaGetSymbolAddress((void**)&optbuf, g_optbuf);
    cudaGetSymbolAddress((void**)&feats,  g_feats);

    // 1-4: s projections
    sgemm_nn<<<dim3(32, 8, 1), 256>>>(s, 384, 0, wq, 2048, 0, qbuf, 2048, 0,
                                      512, 2048, 384, bq);
    sgemm_nn<<<dim3(64, 8, 1), 256>>>(s, 384, 0, wkv, 4096, 0, kvbuf, 4096, 0,
                                      512, 4096, 384, bkv);
    sgemm_nn<<<dim3(3, 8, 1), 256>>>(s, 384, 0, wqp, 192, 0, qpraw, 192, 0,
                                     512, 192, 384, bqp);
    sgemm_nn<<<dim3(8, 8, 1), 256>>>(s, 384, 0, wkvp, 480, 0, kvpraw, 480, 0,
                                     512, 480, 384, bkvp);
    // 5: rigid transform of points
    rigid_kernel<<<(NN * 224 + 255) / 256, 256>>>(qpraw, kvpraw, rot, trans);
    // 6: fused z projections
    zproj_kernel<<<(NN * NN) / 256, 256>>>(z, wb, bb, wz, bz);
    // 7: logits (per-head) with point-attn + bias + mask epilogue
    logits_kernel<<<dim3(8, 8, 8), 256>>>(mask, hwt);
    // 8: softmax over j
    softmax_kernel<<<NH * NN, 256>>>();
    // 9: o = a @ v -> feats[:, h*256 + c]
    sgemm_nn<<<dim3(4, 8, 8), 256>>>(logits, 512, (long)512 * 512,
                                     kvbuf + 256, 4096, 512,
                                     feats, FEAT, 256,
                                     512, 256, 512, nullptr);
    // 10: o_pt = a @ v_pts -> optbuf[h][i][36]
    sgemm_nn<<<dim3(1, 8, 8), 256>>>(logits, 512, (long)512 * 512,
                                     vpts, 288, 36,
                                     optbuf, 36, (long)512 * 36,
                                     512, 36, 512, nullptr);
    // 11: inverse rigid + norms
    optfinal_kernel<<<(NN * 96 + 255) / 256, 256>>>(rot, trans);
    // 12: o_pair
    opair_kernel<<<NN, 256>>>();
    // 13: final projection
    sgemm_nn<<<dim3(6, 8, 1), 256>>>(feats, FEAT, 0, wo, 384, 0, out, 384, 0,
                                     512, 384, FEAT, bo);
}

// round 4
// speedup vs baseline: 1.0252x; 1.0252x over previous
#include <cuda_runtime.h>
#include <cuda_bf16.h>
#include <math.h>

#define NN 512
#define CS 384
#define CZ 128
#define NH 8
#define CH 256
#define PQ_ 8
#define PV_ 12
#define FEAT 2688

// ---------------- scratch ----------------
__device__ float g_qbuf [NN * NH * CH];            // 512 x 2048
__device__ float g_kvbuf[NN * NH * 2 * CH];        // 512 x 4096
__device__ float g_qpraw[NN * NH * PQ_ * 3];       // 512 x 192
__device__ float g_kvpraw[NN * NH * (PQ_+PV_) * 3];// 512 x 480
__device__ float g_qpts [NN * NH * PQ_ * 3];       // [n][h][p][d]
__device__ float g_kpts [NN * NH * PQ_ * 3];
__device__ float g_vpts [NN * NH * PV_ * 3];       // [n][h*36 + p*3+d]
__device__ float g_qnorm[NN * NH];
__device__ float g_knorm[NN * NH];
__device__ float g_biasz[(long)NH * NN * NN];      // [h][i][j]
__device__ float g_logits[(long)NH * NN * NN];     // [h][i][j]
__device__ float g_optbuf[NH * NN * 36];           // [h][i][36]
__device__ float g_feats [NN * FEAT];
__device__ float g_part  [7 * NN * CS];            // split-K partials

// 128x64 tile, 256 threads, 8x4 microtile compute step
#define MICRO_COMPUTE(As, Bs, acc, ty, tx)                                  \
    _Pragma("unroll")                                                       \
    for (int kk = 0; kk < 16; kk++) {                                       \
        float4 a0 = *(const float4*)&As[kk][(ty) * 8];                      \
        float4 a1 = *(const float4*)&As[kk][(ty) * 8 + 4];                  \
        float4 b4 = *(const float4*)&Bs[kk][(tx) * 4];                      \
        float av[8] = {a0.x,a0.y,a0.z,a0.w,a1.x,a1.y,a1.z,a1.w};            \
        float bv[4] = {b4.x,b4.y,b4.z,b4.w};                                \
        _Pragma("unroll")                                                   \
        for (int m = 0; m < 8; m++)                                         \
            _Pragma("unroll")                                               \
            for (int n = 0; n < 4; n++) acc[m][n] += av[m] * bv[n];         \
    }

// ---------------- fused s projections: one GEMM over 6816 cols ----------------
__global__ __launch_bounds__(256) void proj_kernel(
    const float* __restrict__ s,
    const float* __restrict__ wq,  const float* __restrict__ bq,
    const float* __restrict__ wkv, const float* __restrict__ bkv,
    const float* __restrict__ wqp, const float* __restrict__ bqp,
    const float* __restrict__ wkvp,const float* __restrict__ bkvp)
{
    __shared__ float As[16][132];
    __shared__ float Bs[16][68];
    const int tid = threadIdx.x;
    const int tx = tid & 15, ty = tid >> 4;
    const int row0 = blockIdx.y * 128;
    const int bx = blockIdx.x;
    const int col0 = bx * 64;

    const float *B, *bias; float *Cb; int ldb, ldc, nseg, cb;
    if (bx < 32)      { B = wq;   ldb = 2048; bias = bq;   Cb = g_qbuf;   ldc = 2048; cb = col0;        nseg = 2048; }
    else if (bx < 96) { B = wkv;  ldb = 4096; bias = bkv;  Cb = g_kvbuf;  ldc = 4096; cb = col0 - 2048; nseg = 4096; }
    else if (bx < 99) { B = wqp;  ldb = 192;  bias = bqp;  Cb = g_qpraw;  ldc = 192;  cb = col0 - 6144; nseg = 192;  }
    else              { B = wkvp; ldb = 480;  bias = bkvp; Cb = g_kvpraw; ldc = 480;  cb = col0 - 6336; nseg = 480;  }

    float acc[8][4];
#pragma unroll
    for (int m = 0; m < 8; m++)
#pragma unroll
        for (int n = 0; n < 4; n++) acc[m][n] = 0.f;

    for (int k0 = 0; k0 < 384; k0 += 16) {
#pragma unroll
        for (int i = 0; i < 8; i++) {
            int idx = tid + i * 256;
            int r = idx >> 4, kk = idx & 15;
            As[kk][r] = s[(row0 + r) * 384 + k0 + kk];
        }
#pragma unroll
        for (int i = 0; i < 4; i++) {
            int idx = tid + i * 256;
            int kk = idx >> 6, c = idx & 63;
            Bs[kk][c] = (cb + c < nseg) ? B[(long)(k0 + kk) * ldb + cb + c] : 0.f;
        }
        __syncthreads();
        MICRO_COMPUTE(As, Bs, acc, ty, tx);
        __syncthreads();
    }
#pragma unroll
    for (int m = 0; m < 8; m++) {
        int gr = row0 + ty * 8 + m;
#pragma unroll
        for (int n = 0; n < 4; n++) {
            int cc = cb + tx * 4 + n;
            if (cc < nseg) Cb[(long)gr * ldc + cc] = acc[m][n] + bias[cc];
        }
    }
}

// ---------------- rigid transform ----------------
__global__ void rigid_kernel(const float* __restrict__ rot,
                             const float* __restrict__ trans)
{
    int idx = blockIdx.x * 256 + threadIdx.x;
    if (idx >= NN * 224) return;
    int n = idx / 224, p = idx % 224;
    const float* R = rot + n * 9;
    const float* T = trans + n * 3;
    float lx, ly, lz;
    if (p < 64) {
        lx = g_qpraw[n * 192 + p];
        ly = g_qpraw[n * 192 + 64 + p];
        lz = g_qpraw[n * 192 + 128 + p];
    } else {
        int pp = p - 64;
        lx = g_kvpraw[n * 480 + pp];
        ly = g_kvpraw[n * 480 + 160 + pp];
        lz = g_kvpraw[n * 480 + 320 + pp];
    }
    float gx = R[0]*lx + R[1]*ly + R[2]*lz + T[0];
    float gy = R[3]*lx + R[4]*ly + R[5]*lz + T[1];
    float gz = R[6]*lx + R[7]*ly + R[8]*lz + T[2];
    if (p < 64) {
        int h = p >> 3, pq = p & 7;
        float* d = g_qpts + n * 192 + h * 24 + pq * 3;
        d[0] = gx; d[1] = gy; d[2] = gz;
    } else {
        int pp = p - 64;
        int h = pp / 20, q = pp % 20;
        if (q < 8) {
            float* d = g_kpts + n * 192 + h * 24 + q * 3;
            d[0] = gx; d[1] = gy; d[2] = gz;
        } else {
            float* d = g_vpts + n * 288 + h * 36 + (q - 8) * 3;
            d[0] = gx; d[1] = gy; d[2] = gz;
        }
    }
}

// ---------------- per (n,h) point-norm sums ----------------
__global__ void pnorm_kernel()
{
    int idx = blockIdx.x * 256 + threadIdx.x;
    if (idx >= NN * NH) return;
    int n = idx >> 3, h = idx & 7;
    float sq = 0.f, sk = 0.f;
#pragma unroll
    for (int d = 0; d < 24; d++) {
        float a = g_qpts[n * 192 + h * 24 + d];
        float b = g_kpts[n * 192 + h * 24 + d];
        sq += a * a; sk += b * b;
    }
    g_qnorm[idx] = sq; g_knorm[idx] = sk;
}

// ---------------- z bias projection only (8 outputs) ----------------
__global__ __launch_bounds__(256) void zbias_kernel(const float* __restrict__ z,
                             const float* __restrict__ wb, const float* __restrict__ bb)
{
    __shared__ float zs[256][33];   // 33.8KB, conflict-free (t+c)%32
    __shared__ float wbs[128][8];
    int tid = threadIdx.x;
    for (int i = tid; i < 1024; i += 256) wbs[i >> 3][i & 7] = wb[i];
    long pair0 = (long)blockIdx.x * 256;
    float acc[8];
#pragma unroll
    for (int d = 0; d < 8; d++) acc[d] = 0.f;
    for (int ch = 0; ch < 4; ch++) {
#pragma unroll
        for (int l = 0; l < 32; l++) {
            int idx = tid + l * 256;
            int r = idx >> 5, c = idx & 31;
            zs[r][c] = z[(pair0 + r) * 128 + ch * 32 + c];
        }
        __syncthreads();
#pragma unroll
        for (int c = 0; c < 32; c++) {
            float zv = zs[tid][c];
#pragma unroll
            for (int d = 0; d < 8; d++) acc[d] += zv * wbs[ch * 32 + c][d];
        }
        __syncthreads();
    }
#pragma unroll
    for (int d = 0; d < 8; d++)
        g_biasz[(long)d * 262144 + pair0 + tid] = acc[d] + bb[d];
}

// ---------------- logits: augmented-K GEMM (256 chan + 24 point dims) ----------------
__global__ __launch_bounds__(256) void logits_kernel(const float* __restrict__ mask,
                              const float* __restrict__ head_w)
{
    const int h = blockIdx.z;
    __shared__ float As[16][132];
    __shared__ float Bs[16][68];
    __shared__ float qn_s[128], kn_s[64], mi_s[128], mj_s[64];
    const int tid = threadIdx.x;
    const int tx = tid & 15, ty = tid >> 4;
    const int row0 = blockIdx.y * 128;
    const int col0 = blockIdx.x * 64;

    float w = head_w[h];
    float sp = (w > 20.f) ? w : log1pf(__expf(w));
    const float hw = sp * 0.09622504486493762f;   // softplus * sqrt(1/108)
    const float scale = 0.036084391824351615f;     // sqrt(1/768)

    float acc[8][4];
#pragma unroll
    for (int m = 0; m < 8; m++)
#pragma unroll
        for (int n = 0; n < 4; n++) acc[m][n] = 0.f;

    for (int k0 = 0; k0 < 288; k0 += 16) {
#pragma unroll
        for (int i = 0; i < 8; i++) {
            int idx = tid + i * 256;
            int r = idx >> 4, kk = idx & 15;
            int cc = k0 + kk;
            float v;
            if (cc < 256)      v = g_qbuf[(row0 + r) * 2048 + h * 256 + cc] * scale;
            else if (cc < 280) v = g_qpts[(row0 + r) * 192 + h * 24 + (cc - 256)] * hw;
            else               v = 0.f;
            As[kk][r] = v;
        }
#pragma unroll
        for (int i = 0; i < 4; i++) {
            int idx = tid + i * 256;
            int c = idx >> 4, kk = idx & 15;
            int cc = k0 + kk;
            float v;
            if (cc < 256)      v = g_kvbuf[(col0 + c) * 4096 + h * 512 + cc];
            else if (cc < 280) v = g_kpts[(col0 + c) * 192 + h * 24 + (cc - 256)];
            else               v = 0.f;
            Bs[kk][c] = v;
        }
        __syncthreads();
        MICRO_COMPUTE(As, Bs, acc, ty, tx);
        __syncthreads();
    }

    if (tid < 128) { qn_s[tid] = g_qnorm[(row0 + tid) * 8 + h]; mi_s[tid] = mask[row0 + tid]; }
    else if (tid < 192) { int c = tid - 128; kn_s[c] = g_knorm[(col0 + c) * 8 + h]; mj_s[c] = mask[col0 + c]; }
    __syncthreads();

#pragma unroll
    for (int m = 0; m < 8; m++) {
        int lr = ty * 8 + m;
        int gr = row0 + lr;
#pragma unroll
        for (int n = 0; n < 4; n++) {
            int lc = tx * 4 + n;
            int gc = col0 + lc;
            float v = acc[m][n]
                    - 0.5f * hw * (qn_s[lr] + kn_s[lc])
                    + 0.5773502691896258f * g_biasz[(long)h * 262144 + gr * 512 + gc]
                    + 100000.0f * (mi_s[lr] * mj_s[lc] - 1.0f);
            g_logits[((long)h * 512 + gr) * 512 + gc] = v;
        }
    }
}

// ---------------- warp-per-row softmax ----------------
__global__ void softmax_kernel()
{
    int row = blockIdx.x * 8 + (threadIdx.x >> 5);
    int lane = threadIdx.x & 31;
    float* r = g_logits + (long)row * 512;
    float v[16];
    float m = -1e30f;
#pragma unroll
    for (int i = 0; i < 16; i++) { v[i] = r[lane + i * 32]; m = fmaxf(m, v[i]); }
#pragma unroll
    for (int s = 16; s > 0; s >>= 1) m = fmaxf(m, __shfl_xor_sync(0xffffffff, m, s));
    float sum = 0.f;
#pragma unroll
    for (int i = 0; i < 16; i++) { v[i] = __expf(v[i] - m); sum += v[i]; }
#pragma unroll
    for (int s = 16; s > 0; s >>= 1) sum += __shfl_xor_sync(0xffffffff, sum, s);
    float inv = 1.0f / sum;
#pragma unroll
    for (int i = 0; i < 16; i++) r[lane + i * 32] = v[i] * inv;
}

// ---------------- fused o = a@v and o_pt = a@v_pts ----------------
__global__ __launch_bounds__(256) void av_kernel()
{
    const int h = blockIdx.z;
    __shared__ float As[16][132];
    __shared__ float Bs[16][68];
    const int tid = threadIdx.x;
    const int tx = tid & 15, ty = tid >> 4;
    const int row0 = blockIdx.y * 128;
    const int bx = blockIdx.x;
    const int col0 = bx * 64;

    float acc[8][4];
#pragma unroll
    for (int m = 0; m < 8; m++)
#pragma unroll
        for (int n = 0; n < 4; n++) acc[m][n] = 0.f;

    for (int k0 = 0; k0 < 512; k0 += 16) {
#pragma unroll
        for (int i = 0; i < 8; i++) {
            int idx = tid + i * 256;
            int r = idx >> 4, kk = idx & 15;
            As[kk][r] = g_logits[((long)h * 512 + row0 + r) * 512 + k0 + kk];
        }
#pragma unroll
        for (int i = 0; i < 4; i++) {
            int idx = tid + i * 256;
            int kk = idx >> 6, c = idx & 63;
            float v;
            if (bx < 4) v = g_kvbuf[(k0 + kk) * 4096 + h * 512 + 256 + col0 + c];
            else {
                int cc = c;  // col0==256
                v = (cc < 36) ? g_vpts[(k0 + kk) * 288 + h * 36 + cc] : 0.f;
            }
            Bs[kk][c] = v;
        }
        __syncthreads();
        MICRO_COMPUTE(As, Bs, acc, ty, tx);
        __syncthreads();
    }
#pragma unroll
    for (int m = 0; m < 8; m++) {
        int gr = row0 + ty * 8 + m;
#pragma unroll
        for (int n = 0; n < 4; n++) {
            int c = tx * 4 + n;
            if (bx < 4) g_feats[(long)gr * FEAT + h * 256 + col0 + c] = acc[m][n];
            else if (c < 36) g_optbuf[((long)h * 512 + gr) * 36 + c] = acc[m][n];
        }
    }
}

// ---------------- t = a@z then o_pair = t@wz + bz, per row i ----------------
__global__ __launch_bounds__(256) void tz_kernel(const float* __restrict__ z,
                           const float* __restrict__ wz, const float* __restrict__ bz)
{
    __shared__ float a_s[8][512];   // 16KB
    __shared__ float zs[32][128];   // 16KB
    __shared__ float ts[8][128];    // 4KB
    const int i = blockIdx.x;
    const int t = threadIdx.x;
    for (int idx = t; idx < 4096; idx += 256) {
        int h = idx >> 9, j = idx & 511;
        a_s[h][j] = g_logits[((long)h * 512 + i) * 512 + j];
    }
    const int h = t >> 5, cg = t & 31;
    float4 acc = {0.f, 0.f, 0.f, 0.f};
    for (int jc = 0; jc < 512; jc += 32) {
#pragma unroll
        for (int l = 0; l < 16; l++) {
            int idx = t + l * 256;
            int rr = idx >> 7, c = idx & 127;
            zs[rr][c] = z[((long)i * 512 + jc + rr) * 128 + c];
        }
        __syncthreads();
#pragma unroll
        for (int j = 0; j < 32; j++) {
            float a = a_s[h][jc + j];
            float4 zv = *(const float4*)&zs[j][cg * 4];
            acc.x += a * zv.x; acc.y += a * zv.y;
            acc.z += a * zv.z; acc.w += a * zv.w;
        }
        __syncthreads();
    }
    *(float4*)&ts[h][cg * 4] = acc;
    __syncthreads();
    // o_pair = ts @ wz + bz : thread t -> (h2 = t>>5, d = t&31)
    const int h2 = t >> 5, d = t & 31;
    float acc2 = bz[d];
#pragma unroll 4
    for (int c = 0; c < 128; c++) acc2 += ts[h2][c] * wz[c * 32 + d];
    g_feats[(long)i * FEAT + 2432 + t] = acc2;
}

// ---------------- o_pt inverse rigid + norm ----------------
__global__ void optfinal_kernel(const float* __restrict__ rot,
                                const float* __restrict__ trans)
{
    int idx = blockIdx.x * 256 + threadIdx.x;
    if (idx >= NN * 96) return;
    int n = idx / 96, hp = idx % 96;
    int h = hp / 12, p = hp % 12;
    const float* o = g_optbuf + ((long)h * 512 + n) * 36 + p * 3;
    float x = o[0] - trans[n * 3 + 0];
    float y = o[1] - trans[n * 3 + 1];
    float zc = o[2] - trans[n * 3 + 2];
    const float* R = rot + n * 9;
    float ox = R[0] * x + R[3] * y + R[6] * zc;
    float oy = R[1] * x + R[4] * y + R[7] * zc;
    float oz = R[2] * x + R[5] * y + R[8] * zc;
    float* f = g_feats + (long)n * FEAT;
    f[2048 + 0 * 96 + hp] = ox;
    f[2048 + 1 * 96 + hp] = oy;
    f[2048 + 2 * 96 + hp] = oz;
    f[2336 + hp] = sqrtf(ox * ox + oy * oy + oz * oz + 1e-8f);
}

// ---------------- final GEMM, split-K=7 partials ----------------
__global__ __launch_bounds__(256) void fingemm_kernel(const float* __restrict__ wo)
{
    __shared__ float As[16][132];
    __shared__ float Bs[16][68];
    const int tid = threadIdx.x;
    const int tx = tid & 15, ty = tid >> 4;
    const int row0 = blockIdx.y * 128;
    const int col0 = blockIdx.x * 64;
    const int kz = blockIdx.z;
    float* C = g_part + (long)kz * NN * CS;

    float acc[8][4];
#pragma unroll
    for (int m = 0; m < 8; m++)
#pragma unroll
        for (int n = 0; n < 4; n++) acc[m][n] = 0.f;

    for (int k0 = kz * 384; k0 < kz * 384 + 384; k0 += 16) {
#pragma unroll
        for (int i = 0; i < 8; i++) {
            int idx = tid + i * 256;
            int r = idx >> 4, kk = idx & 15;
            As[kk][r] = g_feats[(long)(row0 + r) * FEAT + k0 + kk];
        }
#pragma unroll
        for (int i = 0; i < 4; i++) {
            int idx = tid + i * 256;
            int kk = idx >> 6, c = idx & 63;
            Bs[kk][c] = wo[(long)(k0 + kk) * 384 + col0 + c];
        }
        __syncthreads();
        MICRO_COMPUTE(As, Bs, acc, ty, tx);
        __syncthreads();
    }
#pragma unroll
    for (int m = 0; m < 8; m++) {
        int gr = row0 + ty * 8 + m;
#pragma unroll
        for (int n = 0; n < 4; n++)
            C[(long)gr * 384 + col0 + tx * 4 + n] = acc[m][n];
    }
}

__global__ void reduce_kernel(const float* __restrict__ bo, float* __restrict__ out)
{
    int idx = blockIdx.x * 256 + threadIdx.x;
    if (idx >= NN * CS) return;
    float v = bo[idx % 384];
#pragma unroll
    for (int zc = 0; zc < 7; zc++) v += g_part[(long)zc * NN * CS + idx];
    out[idx] = v;
}

// ---------------- launch ----------------
extern "C" void kernel_launch(void* const* d_in, const int* in_sizes, int n_in,
                              void* d_out, int out_size)
{
    const float* s     = (const float*)d_in[0];
    const float* z     = (const float*)d_in[1];
    const float* rot   = (const float*)d_in[2];
    const float* trans = (const float*)d_in[3];
    const float* mask  = (const float*)d_in[4];
    const float* wq    = (const float*)d_in[5];
    const float* bq    = (const float*)d_in[6];
    const float* wkv   = (const float*)d_in[7];
    const float* bkv   = (const float*)d_in[8];
    const float* wqp   = (const float*)d_in[9];
    const float* bqp   = (const float*)d_in[10];
    const float* wkvp  = (const float*)d_in[11];
    const float* bkvp  = (const float*)d_in[12];
    const float* wb    = (const float*)d_in[13];
    const float* bb    = (const float*)d_in[14];
    const float* wz    = (const float*)d_in[15];
    const float* bz    = (const float*)d_in[16];
    const float* hwt   = (const float*)d_in[17];
    const float* wo    = (const float*)d_in[18];
    const float* bo    = (const float*)d_in[19];
    float* out = (float*)d_out;

    proj_kernel<<<dim3(107, 4), 256>>>(s, wq, bq, wkv, bkv, wqp, bqp, wkvp, bkvp);
    rigid_kernel<<<(NN * 224 + 255) / 256, 256>>>(rot, trans);
    pnorm_kernel<<<(NN * NH + 255) / 256, 256>>>();
    zbias_kernel<<<(NN * NN) / 256, 256>>>(z, wb, bb);
    logits_kernel<<<dim3(8, 4, 8), 256>>>(mask, hwt);
    softmax_kernel<<<512, 256>>>();
    av_kernel<<<dim3(5, 4, 8), 256>>>();
    tz_kernel<<<NN, 256>>>(z, wz, bz);
    optfinal_kernel<<<(NN * 96 + 255) / 256, 256>>>(rot, trans);
    fingemm_kernel<<<dim3(6, 4, 7), 256>>>(wo);
    reduce_kernel<<<(NN * CS + 255) / 256, 256>>>(bo, out);
}

// round 9
// speedup vs baseline: 2.2302x; 2.1755x over previous
#include <cuda_runtime.h>
#include <cuda_bf16.h>
#include <math.h>
#include <stdint.h>

#define NN 512
#define CS 384
#define CZ 128
#define NH 8
#define CH 256
#define PQ_ 8
#define PV_ 12
#define FEAT 2688

// ---------------- scratch ----------------
__device__ float g_qbuf [NN * NH * CH];            // 512 x 2048
__device__ float g_kvbuf[NN * NH * 2 * CH];        // 512 x 4096
__device__ float g_qpraw[NN * NH * PQ_ * 3];       // 512 x 192
__device__ float g_kvpraw[NN * NH * (PQ_+PV_) * 3];// 512 x 480
__device__ float g_qpts [NN * NH * PQ_ * 3];       // [n][h*24 + p*3+d]
__device__ float g_kpts [NN * NH * PQ_ * 3];
__device__ float g_vpts [NN * NH * PV_ * 3];       // [n][h*36 + p*3+d]
__device__ float g_qnorm[NN * NH];
__device__ float g_knorm[NN * NH];
__device__ float g_biasz[(long)NH * NN * NN];      // [h][i][j]
__device__ float g_logits[(long)NH * NN * NN];     // [h][i][j]
__device__ float g_optbuf[NH * NN * 36];           // [h][i][36]
__device__ float g_feats [NN * FEAT];
__device__ float g_part  [4 * NN * CS];            // split-K partials

// ---------------- tf32 helpers ----------------
__device__ __forceinline__ uint32_t to_tf32(float f) {
    uint32_t u;
    asm("cvt.rna.tf32.f32 %0, %1;" : "=r"(u) : "f"(f));
    return u;
}
__device__ __forceinline__ float tf32_hi(float x) {
    return __uint_as_float(to_tf32(x));
}
__device__ __forceinline__ void mma_tf32(float* c, const uint32_t* a, const uint32_t* b) {
    asm volatile(
        "mma.sync.aligned.m16n8k8.row.col.f32.tf32.tf32.f32 "
        "{%0,%1,%2,%3}, {%4,%5,%6,%7}, {%8,%9}, {%0,%1,%2,%3};"
        : "+f"(c[0]), "+f"(c[1]), "+f"(c[2]), "+f"(c[3])
        : "r"(a[0]), "r"(a[1]), "r"(a[2]), "r"(a[3]), "r"(b[0]), "r"(b[1]));
}

// 256 threads = 8 warps as 4x2; block tile 128x64; warp tile 32x32.
// As[16][136] (k-major, pad to stride%32==8 -> conflict-free frag loads)
// Bs[16][72]
#define MMA_DECLS                                              \
    const int tid = threadIdx.x;                               \
    const int lane = tid & 31, wrp = tid >> 5;                 \
    const int wr = wrp >> 1, wc = wrp & 1;                     \
    const int gid = lane >> 2, tig = lane & 3;                 \
    const int rowb = wr * 32, colb = wc * 32;

#define MMA_TILE(As, Bs, acc)                                              \
    {                                                                      \
        _Pragma("unroll")                                                  \
        for (int ks = 0; ks < 2; ks++) {                                   \
            const int kb = ks * 8;                                         \
            uint32_t af[2][4], bf[4][2];                                   \
            _Pragma("unroll")                                              \
            for (int mi = 0; mi < 2; mi++) {                               \
                af[mi][0] = As[kb + tig][rowb + mi * 16 + gid];            \
                af[mi][1] = As[kb + tig][rowb + mi * 16 + gid + 8];        \
                af[mi][2] = As[kb + tig + 4][rowb + mi * 16 + gid];        \
                af[mi][3] = As[kb + tig + 4][rowb + mi * 16 + gid + 8];    \
            }                                                              \
            _Pragma("unroll")                                              \
            for (int ni = 0; ni < 4; ni++) {                               \
                bf[ni][0] = Bs[kb + tig][colb + ni * 8 + gid];             \
                bf[ni][1] = Bs[kb + tig + 4][colb + ni * 8 + gid];         \
            }                                                              \
            _Pragma("unroll")                                              \
            for (int mi = 0; mi < 2; mi++)                                 \
                _Pragma("unroll")                                          \
                for (int ni = 0; ni < 4; ni++)                             \
                    mma_tf32(acc[mi][ni], af[mi], bf[ni]);                 \
        }                                                                  \
    }

// ---------------- fused s projections (tensor) ----------------
__global__ __launch_bounds__(256) void proj_tc(
    const float* __restrict__ s,
    const float* __restrict__ wq,  const float* __restrict__ bq,
    const float* __restrict__ wkv, const float* __restrict__ bkv,
    const float* __restrict__ wqp, const float* __restrict__ bqp,
    const float* __restrict__ wkvp,const float* __restrict__ bkvp)
{
    __shared__ uint32_t As[16][136];
    __shared__ uint32_t Bs[16][72];
    MMA_DECLS;
    const int row0 = blockIdx.y * 128;
    const int bx = blockIdx.x;
    const int col0 = bx * 64;

    const float *B, *bias; float *Cb; int ldb, ldc, nseg, cb;
    if (bx < 32)      { B = wq;   ldb = 2048; bias = bq;   Cb = g_qbuf;   ldc = 2048; cb = col0;        nseg = 2048; }
    else if (bx < 96) { B = wkv;  ldb = 4096; bias = bkv;  Cb = g_kvbuf;  ldc = 4096; cb = col0 - 2048; nseg = 4096; }
    else if (bx < 99) { B = wqp;  ldb = 192;  bias = bqp;  Cb = g_qpraw;  ldc = 192;  cb = col0 - 6144; nseg = 192;  }
    else              { B = wkvp; ldb = 480;  bias = bkvp; Cb = g_kvpraw; ldc = 480;  cb = col0 - 6336; nseg = 480;  }

    float acc[2][4][4];
#pragma unroll
    for (int mi = 0; mi < 2; mi++)
#pragma unroll
        for (int ni = 0; ni < 4; ni++)
#pragma unroll
            for (int e = 0; e < 4; e++) acc[mi][ni][e] = 0.f;

    for (int k0 = 0; k0 < 384; k0 += 16) {
#pragma unroll
        for (int i = 0; i < 8; i++) {
            int idx = tid + i * 256;
            int r = idx >> 4, kk = idx & 15;
            As[kk][r] = to_tf32(s[(row0 + r) * 384 + k0 + kk]);
        }
#pragma unroll
        for (int i = 0; i < 4; i++) {
            int idx = tid + i * 256;
            int kk = idx >> 6, c = idx & 63;
            Bs[kk][c] = (cb + c < nseg) ? to_tf32(B[(long)(k0 + kk) * ldb + cb + c]) : 0u;
        }
        __syncthreads();
        MMA_TILE(As, Bs, acc);
        __syncthreads();
    }
#pragma unroll
    for (int mi = 0; mi < 2; mi++) {
        int r0 = row0 + rowb + mi * 16 + gid;
#pragma unroll
        for (int ni = 0; ni < 4; ni++) {
            int c0 = cb + colb + ni * 8 + 2 * tig;
#pragma unroll
            for (int e = 0; e < 4; e++) {
                int gr = r0 + (e >> 1) * 8;
                int cc = c0 + (e & 1);
                if (cc < nseg) Cb[(long)gr * ldc + cc] = acc[mi][ni][e] + bias[cc];
            }
        }
    }
}

// ---------------- rigid transform ----------------
__global__ void rigid_kernel(const float* __restrict__ rot,
                             const float* __restrict__ trans)
{
    int idx = blockIdx.x * 256 + threadIdx.x;
    if (idx >= NN * 224) return;
    int n = idx / 224, p = idx % 224;
    const float* R = rot + n * 9;
    const float* T = trans + n * 3;
    float lx, ly, lz;
    if (p < 64) {
        lx = g_qpraw[n * 192 + p];
        ly = g_qpraw[n * 192 + 64 + p];
        lz = g_qpraw[n * 192 + 128 + p];
    } else {
        int pp = p - 64;
        lx = g_kvpraw[n * 480 + pp];
        ly = g_kvpraw[n * 480 + 160 + pp];
        lz = g_kvpraw[n * 480 + 320 + pp];
    }
    float gx = R[0]*lx + R[1]*ly + R[2]*lz + T[0];
    float gy = R[3]*lx + R[4]*ly + R[5]*lz + T[1];
    float gz = R[6]*lx + R[7]*ly + R[8]*lz + T[2];
    if (p < 64) {
        int h = p >> 3, pq = p & 7;
        float* d = g_qpts + n * 192 + h * 24 + pq * 3;
        d[0] = gx; d[1] = gy; d[2] = gz;
    } else {
        int pp = p - 64;
        int h = pp / 20, q = pp % 20;
        if (q < 8) {
            float* d = g_kpts + n * 192 + h * 24 + q * 3;
            d[0] = gx; d[1] = gy; d[2] = gz;
        } else {
            float* d = g_vpts + n * 288 + h * 36 + (q - 8) * 3;
            d[0] = gx; d[1] = gy; d[2] = gz;
        }
    }
}

// ---------------- per (n,h) point-norm sums (exact fp32) ----------------
__global__ void pnorm_kernel()
{
    int idx = blockIdx.x * 256 + threadIdx.x;
    if (idx >= NN * NH) return;
    int n = idx >> 3, h = idx & 7;
    float sq = 0.f, sk = 0.f;
#pragma unroll
    for (int d = 0; d < 24; d++) {
        float a = g_qpts[n * 192 + h * 24 + d];
        float b = g_kpts[n * 192 + h * 24 + d];
        sq += a * a; sk += b * b;
    }
    g_qnorm[idx] = sq; g_knorm[idx] = sk;
}

// ---------------- z bias projection (vectorized staging) ----------------
__global__ __launch_bounds__(256) void zbias_kernel(const float* __restrict__ z,
                             const float* __restrict__ wb, const float* __restrict__ bb)
{
    __shared__ float zs[256][33];
    __shared__ float wbs[128][8];
    int tid = threadIdx.x;
    for (int i = tid; i < 1024; i += 256) wbs[i >> 3][i & 7] = wb[i];
    long pair0 = (long)blockIdx.x * 256;
    float acc[8];
#pragma unroll
    for (int d = 0; d < 8; d++) acc[d] = 0.f;
    for (int ch = 0; ch < 4; ch++) {
#pragma unroll
        for (int l = 0; l < 8; l++) {
            int idx = tid + l * 256;       // 2048 float4 slots
            int r = idx >> 3, c4 = idx & 7;
            float4 v = *(const float4*)(z + (pair0 + r) * 128 + ch * 32 + c4 * 4);
            zs[r][c4 * 4 + 0] = v.x; zs[r][c4 * 4 + 1] = v.y;
            zs[r][c4 * 4 + 2] = v.z; zs[r][c4 * 4 + 3] = v.w;
        }
        __syncthreads();
#pragma unroll
        for (int c = 0; c < 32; c++) {
            float zv = zs[tid][c];
#pragma unroll
            for (int d = 0; d < 8; d++) acc[d] += zv * wbs[ch * 32 + c][d];
        }
        __syncthreads();
    }
#pragma unroll
    for (int d = 0; d < 8; d++)
        g_biasz[(long)d * 262144 + pair0 + tid] = acc[d] + bb[d];
}

// ---------------- logits: tensor QK + 2xTF32 point cross-term ----------------
__global__ __launch_bounds__(256) void logits_tc(const float* __restrict__ mask,
                              const float* __restrict__ head_w)
{
    const int h = blockIdx.z;
    __shared__ uint32_t As[16][136];
    __shared__ uint32_t Bs[16][72];
    __shared__ float qn_s[128], kn_s[64], mi_s[128], mj_s[64];
    MMA_DECLS;
    const int row0 = blockIdx.y * 128;
    const int col0 = blockIdx.x * 64;

    float w = head_w[h];
    float sp = (w > 20.f) ? w : log1pf(__expf(w));
    const float hw = sp * 0.09622504486493762f;    // softplus * sqrt(1/108)
    const float qscale = 0.036084391824351615f;    // sqrt(1/768)

    if (tid < 128) { qn_s[tid] = g_qnorm[(row0 + tid) * 8 + h]; mi_s[tid] = mask[row0 + tid]; }
    else if (tid < 192) { int c = tid - 128; kn_s[c] = g_knorm[(col0 + c) * 8 + h]; mj_s[c] = mask[col0 + c]; }

    float acc[2][4][4], accP[2][4][4];
#pragma unroll
    for (int mi = 0; mi < 2; mi++)
#pragma unroll
        for (int ni = 0; ni < 4; ni++)
#pragma unroll
            for (int e = 0; e < 4; e++) { acc[mi][ni][e] = 0.f; accP[mi][ni][e] = 0.f; }

    // phase 1: 256-dim QK (q pre-scaled)
    for (int k0 = 0; k0 < 256; k0 += 16) {
#pragma unroll
        for (int i = 0; i < 8; i++) {
            int idx = tid + i * 256;
            int r = idx >> 4, kk = idx & 15;
            As[kk][r] = to_tf32(g_qbuf[(row0 + r) * 2048 + h * 256 + k0 + kk] * qscale);
        }
#pragma unroll
        for (int i = 0; i < 4; i++) {
            int idx = tid + i * 256;
            int c = idx >> 4, kk = idx & 15;
            Bs[kk][c] = to_tf32(g_kvbuf[(col0 + c) * 4096 + h * 512 + k0 + kk]);
        }
        __syncthreads();
        MMA_TILE(As, Bs, acc);
        __syncthreads();
    }
    // phase 2: point cross-term, 24 dims x (hi*hi + lo*hi + hi*lo) = 72 (pad 80)
    for (int k0 = 0; k0 < 80; k0 += 16) {
#pragma unroll
        for (int i = 0; i < 8; i++) {
            int idx = tid + i * 256;
            int r = idx >> 4, kk = idx & 15;
            int cc = k0 + kk;
            uint32_t v = 0u;
            if (cc < 72) {
                int sel = cc / 24, pd = cc % 24;
                float x = g_qpts[(row0 + r) * 192 + h * 24 + pd];
                float hi = tf32_hi(x);
                v = (sel == 1) ? to_tf32(x - hi) : __float_as_uint(hi);
            }
            As[kk][r] = v;
        }
#pragma unroll
        for (int i = 0; i < 4; i++) {
            int idx = tid + i * 256;
            int c = idx >> 4, kk = idx & 15;
            int cc = k0 + kk;
            uint32_t v = 0u;
            if (cc < 72) {
                int sel = cc / 24, pd = cc % 24;
                float x = g_kpts[(col0 + c) * 192 + h * 24 + pd];
                float hi = tf32_hi(x);
                v = (sel == 2) ? to_tf32(x - hi) : __float_as_uint(hi);
            }
            Bs[kk][c] = v;
        }
        __syncthreads();
        MMA_TILE(As, Bs, accP);
        __syncthreads();
    }

#pragma unroll
    for (int mi = 0; mi < 2; mi++) {
#pragma unroll
        for (int ni = 0; ni < 4; ni++) {
#pragma unroll
            for (int e = 0; e < 4; e++) {
                int lr = rowb + mi * 16 + gid + (e >> 1) * 8;
                int lc = colb + ni * 8 + 2 * tig + (e & 1);
                int gr = row0 + lr, gc = col0 + lc;
                float v = acc[mi][ni][e]
                        + hw * accP[mi][ni][e]
                        - 0.5f * hw * (qn_s[lr] + kn_s[lc])
                        + 0.5773502691896258f * g_biasz[(long)h * 262144 + gr * 512 + gc]
                        + 100000.0f * (mi_s[lr] * mj_s[lc] - 1.0f);
                g_logits[((long)h * 512 + gr) * 512 + gc] = v;
            }
        }
    }
}

// ---------------- warp-per-row softmax ----------------
__global__ void softmax_kernel()
{
    int row = blockIdx.x * 8 + (threadIdx.x >> 5);
    int lane = threadIdx.x & 31;
    float* r = g_logits + (long)row * 512;
    float v[16];
    float m = -1e30f;
#pragma unroll
    for (int i = 0; i < 16; i++) { v[i] = r[lane + i * 32]; m = fmaxf(m, v[i]); }
#pragma unroll
    for (int s = 16; s > 0; s >>= 1) m = fmaxf(m, __shfl_xor_sync(0xffffffff, m, s));
    float sum = 0.f;
#pragma unroll
    for (int i = 0; i < 16; i++) { v[i] = __expf(v[i] - m); sum += v[i]; }
#pragma unroll
    for (int s = 16; s > 0; s >>= 1) sum += __shfl_xor_sync(0xffffffff, sum, s);
    float inv = 1.0f / sum;
#pragma unroll
    for (int i = 0; i < 16; i++) r[lane + i * 32] = v[i] * inv;
}

// ---------------- o = a @ v (tensor) ----------------
__global__ __launch_bounds__(256) void av_tc()
{
    const int h = blockIdx.z;
    __shared__ uint32_t As[16][136];
    __shared__ uint32_t Bs[16][72];
    MMA_DECLS;
    const int row0 = blockIdx.y * 128;
    const int col0 = blockIdx.x * 64;

    float acc[2][4][4];
#pragma unroll
    for (int mi = 0; mi < 2; mi++)
#pragma unroll
        for (int ni = 0; ni < 4; ni++)
#pragma unroll
            for (int e = 0; e < 4; e++) acc[mi][ni][e] = 0.f;

    for (int k0 = 0; k0 < 512; k0 += 16) {
#pragma unroll
        for (int i = 0; i < 8; i++) {
            int idx = tid + i * 256;
            int r = idx >> 4, kk = idx & 15;
            As[kk][r] = to_tf32(g_logits[((long)h * 512 + row0 + r) * 512 + k0 + kk]);
        }
#pragma unroll
        for (int i = 0; i < 4; i++) {
            int idx = tid + i * 256;
            int kk = idx >> 6, c = idx & 63;
            Bs[kk][c] = to_tf32(g_kvbuf[(k0 + kk) * 4096 + h * 512 + 256 + col0 + c]);
        }
        __syncthreads();
        MMA_TILE(As, Bs, acc);
        __syncthreads();
    }
#pragma unroll
    for (int mi = 0; mi < 2; mi++) {
        int r0 = row0 + rowb + mi * 16 + gid;
#pragma unroll
        for (int ni = 0; ni < 4; ni++) {
            int c0 = col0 + colb + ni * 8 + 2 * tig;
#pragma unroll
            for (int e = 0; e < 4; e++) {
                int gr = r0 + (e >> 1) * 8;
                int cc = c0 + (e & 1);
                g_feats[(long)gr * FEAT + h * 256 + cc] = acc[mi][ni][e];
            }
        }
    }
}

// ---------------- o_pt = a @ v_pts (fp32, cancellation-sensitive) ----------------
__global__ __launch_bounds__(288) void optgemm_kernel()
{
    __shared__ float a_s[8][512];
    __shared__ float vs[128][36];
    const int h = blockIdx.y;
    const int i0 = blockIdx.x * 8;
    const int t = threadIdx.x;
    for (int idx = t; idx < 4096; idx += 288) {
        int r = idx >> 9, k = idx & 511;
        a_s[r][k] = g_logits[((long)h * 512 + i0 + r) * 512 + k];
    }
    const int r = t / 36, c = t % 36;
    float acc = 0.f;
    for (int kc = 0; kc < 512; kc += 128) {
        __syncthreads();
        for (int idx = t; idx < 128 * 36; idx += 288) {
            int rr = idx / 36, cc = idx % 36;
            vs[rr][cc] = g_vpts[(kc + rr) * 288 + h * 36 + cc];
        }
        __syncthreads();
#pragma unroll 8
        for (int kk = 0; kk < 128; kk++) acc += a_s[r][kc + kk] * vs[kk][c];
    }
    g_optbuf[((long)h * 512 + i0 + r) * 36 + c] = acc;
}

// ---------------- t = a@z, o_pair = t@wz + bz (vectorized staging) ----------------
__global__ __launch_bounds__(256) void tz_kernel(const float* __restrict__ z,
                           const float* __restrict__ wz, const float* __restrict__ bz)
{
    __shared__ float a_s[8][512];
    __shared__ float zs[32][128];
    __shared__ float ts[8][128];
    const int i = blockIdx.x;
    const int t = threadIdx.x;
    for (int idx = t; idx < 4096; idx += 256) {
        int h = idx >> 9, j = idx & 511;
        a_s[h][j] = g_logits[((long)h * 512 + i) * 512 + j];
    }
    const int h = t >> 5, cg = t & 31;
    float4 acc = {0.f, 0.f, 0.f, 0.f};
    for (int jc = 0; jc < 512; jc += 32) {
#pragma unroll
        for (int l = 0; l < 4; l++) {
            int idx = t + l * 256;          // 1024 float4 slots
            int rr = idx >> 5, c4 = idx & 31;
            *(float4*)&zs[rr][c4 * 4] =
                *(const float4*)(z + ((long)i * 512 + jc + rr) * 128 + c4 * 4);
        }
        __syncthreads();
#pragma unroll
        for (int j = 0; j < 32; j++) {
            float a = a_s[h][jc + j];
            float4 zv = *(const float4*)&zs[j][cg * 4];
            acc.x += a * zv.x; acc.y += a * zv.y;
            acc.z += a * zv.z; acc.w += a * zv.w;
        }
        __syncthreads();
    }
    *(float4*)&ts[h][cg * 4] = acc;
    __syncthreads();
    const int h2 = t >> 5, d = t & 31;
    float acc2 = bz[d];
#pragma unroll 4
    for (int c = 0; c < 128; c++) acc2 += ts[h2][c] * wz[c * 32 + d];
    g_feats[(long)i * FEAT + 2432 + t] = acc2;
}

// ---------------- o_pt inverse rigid + norm ----------------
__global__ void optfinal_kernel(const float* __restrict__ rot,
                                const float* __restrict__ trans)
{
    int idx = blockIdx.x * 256 + threadIdx.x;
    if (idx >= NN * 96) return;
    int n = idx / 96, hp = idx % 96;
    int h = hp / 12, p = hp % 12;
    const float* o = g_optbuf + ((long)h * 512 + n) * 36 + p * 3;
    float x = o[0] - trans[n * 3 + 0];
    float y = o[1] - trans[n * 3 + 1];
    float zc = o[2] - trans[n * 3 + 2];
    const float* R = rot + n * 9;
    float ox = R[0] * x + R[3] * y + R[6] * zc;
    float oy = R[1] * x + R[4] * y + R[7] * zc;
    float oz = R[2] * x + R[5] * y + R[8] * zc;
    float* f = g_feats + (long)n * FEAT;
    f[2048 + 0 * 96 + hp] = ox;
    f[2048 + 1 * 96 + hp] = oy;
    f[2048 + 2 * 96 + hp] = oz;
    f[2336 + hp] = sqrtf(ox * ox + oy * oy + oz * oz + 1e-8f);
}

// ---------------- final GEMM (tensor, split-K=4) ----------------
__global__ __launch_bounds__(256) void fingemm_tc(const float* __restrict__ wo)
{
    __shared__ uint32_t As[16][136];
    __shared__ uint32_t Bs[16][72];
    MMA_DECLS;
    const int row0 = blockIdx.y * 128;
    const int col0 = blockIdx.x * 64;
    const int kz = blockIdx.z;
    float* C = g_part + (long)kz * NN * CS;

    float acc[2][4][4];
#pragma unroll
    for (int mi = 0; mi < 2; mi++)
#pragma unroll
        for (int ni = 0; ni < 4; ni++)
#pragma unroll
            for (int e = 0; e < 4; e++) acc[mi][ni][e] = 0.f;

    for (int k0 = kz * 672; k0 < kz * 672 + 672; k0 += 16) {
#pragma unroll
        for (int i = 0; i < 8; i++) {
            int idx = tid + i * 256;
            int r = idx >> 4, kk = idx & 15;
            As[kk][r] = to_tf32(g_feats[(long)(row0 + r) * FEAT + k0 + kk]);
        }
#pragma unroll
        for (int i = 0; i < 4; i++) {
            int idx = tid + i * 256;
            int kk = idx >> 6, c = idx & 63;
            Bs[kk][c] = to_tf32(wo[(long)(k0 + kk) * 384 + col0 + c]);
        }
        __syncthreads();
        MMA_TILE(As, Bs, acc);
        __syncthreads();
    }
#pragma unroll
    for (int mi = 0; mi < 2; mi++) {
        int r0 = row0 + rowb + mi * 16 + gid;
#pragma unroll
        for (int ni = 0; ni < 4; ni++) {
            int c0 = col0 + colb + ni * 8 + 2 * tig;
#pragma unroll
            for (int e = 0; e < 4; e++)
                C[(long)(r0 + (e >> 1) * 8) * 384 + c0 + (e & 1)] = acc[mi][ni][e];
        }
    }
}

__global__ void reduce_kernel(const float* __restrict__ bo, float* __restrict__ out)
{
    int idx = blockIdx.x * 256 + threadIdx.x;
    if (idx >= NN * CS) return;
    float v = bo[idx % 384];
#pragma unroll
    for (int zc = 0; zc < 4; zc++) v += g_part[(long)zc * NN * CS + idx];
    out[idx] = v;
}

// ---------------- launch ----------------
extern "C" void kernel_launch(void* const* d_in, const int* in_sizes, int n_in,
                              void* d_out, int out_size)
{
    const float* s     = (const float*)d_in[0];
    const float* z     = (const float*)d_in[1];
    const float* rot   = (const float*)d_in[2];
    const float* trans = (const float*)d_in[3];
    const float* mask  = (const float*)d_in[4];
    const float* wq    = (const float*)d_in[5];
    const float* bq    = (const float*)d_in[6];
    const float* wkv   = (const float*)d_in[7];
    const float* bkv   = (const float*)d_in[8];
    const float* wqp   = (const float*)d_in[9];
    const float* bqp   = (const float*)d_in[10];
    const float* wkvp  = (const float*)d_in[11];
    const float* bkvp  = (const float*)d_in[12];
    const float* wb    = (const float*)d_in[13];
    const float* bb    = (const float*)d_in[14];
    const float* wz    = (const float*)d_in[15];
    const float* bz    = (const float*)d_in[16];
    const float* hwt   = (const float*)d_in[17];
    const float* wo    = (const float*)d_in[18];
    const float* bo    = (const float*)d_in[19];
    float* out = (float*)d_out;

    proj_tc<<<dim3(107, 4), 256>>>(s, wq, bq, wkv, bkv, wqp, bqp, wkvp, bkvp);
    rigid_kernel<<<(NN * 224 + 255) / 256, 256>>>(rot, trans);
    pnorm_kernel<<<(NN * NH + 255) / 256, 256>>>();
    zbias_kernel<<<(NN * NN) / 256, 256>>>(z, wb, bb);
    logits_tc<<<dim3(8, 4, 8), 256>>>(mask, hwt);
    softmax_kernel<<<512, 256>>>();
    av_tc<<<dim3(4, 4, 8), 256>>>();
    optgemm_kernel<<<dim3(64, 8), 288>>>();
    tz_kernel<<<NN, 256>>>(z, wz, bz);
    optfinal_kernel<<<(NN * 96 + 255) / 256, 256>>>(rot, trans);
    fingemm_tc<<<dim3(6, 4, 4), 256>>>(wo);
    reduce_kernel<<<(NN * CS + 255) / 256, 256>>>(bo, out);
}